// round 3
// baseline (speedup 1.0000x reference)
#include <cuda_runtime.h>
#include <math.h>

// Problem dims (fixed by reference)
#define Bb 2
#define Dd 256
#define Tt 8
#define HW 1024          // H*W = 32*32
#define NROWS 16384      // B*T*H*W
#define KCODES 8192

// ---------------- scratch (__device__ globals; no allocation allowed) ----------------
__device__ float g_zf[NROWS * Dd];          // z transposed to [N, D]
__device__ float g_zq[NROWS * Dd];          // gathered codes [N, D]
__device__ float g_Hb[KCODES * Dd];         // gelu(emb @ w1^T)
__device__ float g_Cb[KCODES * Dd];         // codebook [K, D]
__device__ float g_cn2[KCODES];             // ||c_k||^2
__device__ unsigned long long g_rowmin[NROWS];
__device__ int g_counts[KCODES];
__device__ float g_zsum[Dd];
__device__ float g_csum[Dd];
__device__ double g_z2sum;
__device__ double g_losssum;

// ---------------- init ----------------
__global__ void init_kernel() {
    int i = blockIdx.x * 256 + threadIdx.x;
    if (i < NROWS) g_rowmin[i] = ~0ULL;
    if (i < KCODES) g_counts[i] = 0;
    if (i < Dd) { g_zsum[i] = 0.f; g_csum[i] = 0.f; }
    if (i == 0) { g_z2sum = 0.0; g_losssum = 0.0; }
}

// ---------------- transpose z [B,D,T,H,W] -> zf [N, D] ----------------
__global__ void transpose_in_kernel(const float* __restrict__ z) {
    __shared__ float tile[32][33];
    int bt = blockIdx.z;
    int b = bt / Tt, t = bt % Tt;
    int hw0 = blockIdx.x * 32, d0 = blockIdx.y * 32;
    const float* src = z + (size_t)b * Dd * Tt * HW + (size_t)t * HW;
    // tile[d_local][hw_local] = z[d0+d][hw0+hw]
    for (int r = threadIdx.y; r < 32; r += 8)
        tile[r][threadIdx.x] = src[(size_t)(d0 + r) * (Tt * HW) + hw0 + threadIdx.x];
    __syncthreads();
    float* dst = g_zf + (size_t)bt * HW * Dd;
    for (int r = threadIdx.y; r < 32; r += 8)
        dst[(size_t)(hw0 + r) * Dd + d0 + threadIdx.x] = tile[threadIdx.x][r];
}

// ---------------- transpose zq [N,D] -> out [B,D,T,H,W] ----------------
__global__ void transpose_out_kernel(float* __restrict__ out) {
    __shared__ float tile[32][33];
    int bt = blockIdx.z;
    int b = bt / Tt, t = bt % Tt;
    int hw0 = blockIdx.x * 32, d0 = blockIdx.y * 32;
    const float* src = g_zq + (size_t)bt * HW * Dd;
    // tile[hw_local][d_local]
    for (int r = threadIdx.y; r < 32; r += 8)
        tile[r][threadIdx.x] = src[(size_t)(hw0 + r) * Dd + d0 + threadIdx.x];
    __syncthreads();
    float* dst = out + (size_t)b * Dd * Tt * HW + (size_t)t * HW;
    for (int r = threadIdx.y; r < 32; r += 8)
        dst[(size_t)(d0 + r) * (Tt * HW) + hw0 + threadIdx.x] = tile[threadIdx.x][r];
}

// ---------------- column sums (+ optional total sum of squares) ----------------
// one block handles 64 rows; thread t owns column t (coalesced reads)
__global__ void colsum_z_kernel() {
    int tid = threadIdx.x;
    int row0 = blockIdx.x * 64;
    float s = 0.f, sq = 0.f;
    for (int r = 0; r < 64; r++) {
        float v = g_zf[(size_t)(row0 + r) * Dd + tid];
        s += v; sq += v * v;
    }
    atomicAdd(&g_zsum[tid], s);
    __shared__ float red[256];
    red[tid] = sq; __syncthreads();
    for (int o = 128; o; o >>= 1) { if (tid < o) red[tid] += red[tid + o]; __syncthreads(); }
    if (tid == 0) atomicAdd(&g_z2sum, (double)red[0]);
}

__global__ void colsum_c_kernel() {
    int tid = threadIdx.x;
    int row0 = blockIdx.x * 64;
    float s = 0.f;
    for (int r = 0; r < 64; r++) s += g_Cb[(size_t)(row0 + r) * Dd + tid];
    atomicAdd(&g_csum[tid], s);
}

// ---------------- per-row ||c||^2 ----------------
__global__ void rownorm_kernel() {
    int row = blockIdx.x * 8 + (threadIdx.x >> 5);
    int lane = threadIdx.x & 31;
    const float* p = g_Cb + (size_t)row * Dd;
    float s = 0.f;
    for (int i = lane; i < Dd; i += 32) { float v = p[i]; s += v * v; }
    for (int o = 16; o; o >>= 1) s += __shfl_down_sync(0xFFFFFFFFu, s, o);
    if (lane == 0) g_cn2[row] = s;
}

// ---------------- SGEMM  C = A[M,256] * B[N,256]^T ----------------
// MODE 0: store plain; MODE 1: store gelu; MODE 2: fused distance-argmin, no store.
#define BM 128
#define BN 128
#define BKk 16

__device__ __forceinline__ unsigned int float_key(float f) {
    unsigned int b = __float_as_uint(f);
    return (b & 0x80000000u) ? ~b : (b | 0x80000000u);
}

template<int MODE>
__global__ __launch_bounds__(256) void gemm_nt_kernel(
    const float* __restrict__ A, const float* __restrict__ B, float* __restrict__ Cout)
{
    __shared__ __align__(16) float sA[BKk][BM];
    __shared__ __align__(16) float sB[BKk][BN];
    int tid = threadIdx.x;
    int tx = tid & 15, ty = tid >> 4;
    int m0 = blockIdx.y * BM;
    int n0 = blockIdx.x * BN;

    float acc[8][8];
#pragma unroll
    for (int i = 0; i < 8; i++)
#pragma unroll
        for (int j = 0; j < 8; j++) acc[i][j] = 0.f;

    const float* Ab = A + (size_t)m0 * Dd;
    const float* Bt = B + (size_t)n0 * Dd;

    for (int kt = 0; kt < Dd; kt += BKk) {
#pragma unroll
        for (int s = 0; s < 2; s++) {
            int v = tid + s * 256;           // 0..511
            int row = v >> 2;                // 0..127
            int kq = (v & 3) << 2;           // 0,4,8,12
            float4 fa = *(const float4*)(Ab + (size_t)row * Dd + kt + kq);
            sA[kq + 0][row] = fa.x; sA[kq + 1][row] = fa.y;
            sA[kq + 2][row] = fa.z; sA[kq + 3][row] = fa.w;
            float4 fb = *(const float4*)(Bt + (size_t)row * Dd + kt + kq);
            sB[kq + 0][row] = fb.x; sB[kq + 1][row] = fb.y;
            sB[kq + 2][row] = fb.z; sB[kq + 3][row] = fb.w;
        }
        __syncthreads();
#pragma unroll
        for (int kk = 0; kk < BKk; kk++) {
            float ra[8], rb[8];
#pragma unroll
            for (int i = 0; i < 8; i++) ra[i] = sA[kk][ty * 8 + i];
#pragma unroll
            for (int j = 0; j < 8; j++) rb[j] = sB[kk][tx * 8 + j];
#pragma unroll
            for (int i = 0; i < 8; i++)
#pragma unroll
                for (int j = 0; j < 8; j++) acc[i][j] += ra[i] * rb[j];
        }
        __syncthreads();
    }

    if (MODE == 2) {
        // fused argmin of (||c||^2 - 2 z.c); pack (ordered-key, idx) -> atomicMin
#pragma unroll
        for (int i = 0; i < 8; i++) {
            unsigned long long best = ~0ULL;
#pragma unroll
            for (int j = 0; j < 8; j++) {
                int k = n0 + tx * 8 + j;
                float dist = g_cn2[k] - 2.0f * acc[i][j];
                unsigned long long p =
                    ((unsigned long long)float_key(dist) << 32) | (unsigned int)k;
                best = p < best ? p : best;
            }
#pragma unroll
            for (int off = 8; off; off >>= 1) {
                unsigned long long o = __shfl_down_sync(0xFFFFFFFFu, best, off);
                best = o < best ? o : best;
            }
            if (tx == 0) atomicMin(&g_rowmin[m0 + ty * 8 + i], best);
        }
    } else {
#pragma unroll
        for (int i = 0; i < 8; i++)
#pragma unroll
            for (int j = 0; j < 8; j++) {
                float v = acc[i][j];
                if (MODE == 1) v = 0.5f * v * (1.0f + erff(v * 0.70710678118654752f));
                Cout[(size_t)(m0 + ty * 8 + i) * Dd + n0 + tx * 8 + j] = v;
            }
    }
}

// ---------------- gather chosen codes, loss partials, histogram ----------------
__global__ void gather_kernel() {
    int tid = threadIdx.x;
    float lsum = 0.f;
#pragma unroll
    for (int r = 0; r < 8; r++) {
        int n = blockIdx.x * 8 + r;
        unsigned int idx = (unsigned int)(g_rowmin[n] & 0xFFFFFFFFULL);
        float c = g_Cb[(size_t)idx * Dd + tid];
        float zv = g_zf[(size_t)n * Dd + tid];
        g_zq[(size_t)n * Dd + tid] = zv + (c - zv);   // replicate STE rounding
        float d = c - zv;
        lsum += d * d;
        if (tid == 0) atomicAdd(&g_counts[idx], 1);
    }
    __shared__ float red[256];
    red[tid] = lsum; __syncthreads();
    for (int o = 128; o; o >>= 1) { if (tid < o) red[tid] += red[tid + o]; __syncthreads(); }
    if (tid == 0) atomicAdd(&g_losssum, (double)red[0]);
}

// ---------------- scalars ----------------
__global__ void finalize_kernel(float* __restrict__ out_scalars) {
    __shared__ double red[256];
    int tid = threadIdx.x;

    double s = 0.0;
    for (int k = tid; k < KCODES; k += 256) s += (double)g_cn2[k];
    red[tid] = s; __syncthreads();
    for (int o = 128; o; o >>= 1) { if (tid < o) red[tid] += red[tid + o]; __syncthreads(); }
    double c2sum = red[0]; __syncthreads();

    red[tid] = (double)g_zsum[tid] * (double)g_csum[tid]; __syncthreads();
    for (int o = 128; o; o >>= 1) { if (tid < o) red[tid] += red[tid + o]; __syncthreads(); }
    double dot = red[0]; __syncthreads();

    double e = 0.0;
    for (int k = tid; k < KCODES; k += 256) {
        float p = (float)g_counts[k] / (float)NROWS;
        e += (double)(p * logf(p + 1e-10f));
    }
    red[tid] = e; __syncthreads();
    for (int o = 128; o; o >>= 1) { if (tid < o) red[tid] += red[tid + o]; __syncthreads(); }
    double ent = red[0];

    if (tid == 0) {
        double loss = 1.25 * g_losssum / ((double)NROWS * (double)Dd);
        double md = g_z2sum / (double)NROWS + c2sum / (double)KCODES
                  - 2.0 * dot / ((double)NROWS * (double)KCODES);
        out_scalars[0] = (float)loss;
        out_scalars[1] = expf((float)(-ent));
        out_scalars[2] = (float)md;
    }
}

// ---------------- launcher ----------------
extern "C" void kernel_launch(void* const* d_in, const int* in_sizes, int n_in,
                              void* d_out, int out_size) {
    const float* z    = (const float*)d_in[0];   // [2,256,8,32,32]
    const float* emb  = (const float*)d_in[1];   // [8192,256]
    const float* w1   = (const float*)d_in[2];   // [256,256]
    const float* w2   = (const float*)d_in[3];   // [256,256]
    float* out = (float*)d_out;

    static float *zf = nullptr, *Hb = nullptr, *Cb = nullptr;
    if (!zf) {
        cudaGetSymbolAddress((void**)&zf, g_zf);
        cudaGetSymbolAddress((void**)&Hb, g_Hb);
        cudaGetSymbolAddress((void**)&Cb, g_Cb);
    }

    init_kernel<<<64, 256>>>();
    transpose_in_kernel<<<dim3(HW / 32, Dd / 32, Bb * Tt), dim3(32, 8)>>>(z);
    colsum_z_kernel<<<NROWS / 64, 256>>>();

    // codebook: H = gelu(emb @ w1^T); C = H @ w2^T
    gemm_nt_kernel<1><<<dim3(Dd / BN, KCODES / BM), 256>>>(emb, w1, Hb);
    gemm_nt_kernel<0><<<dim3(Dd / BN, KCODES / BM), 256>>>(Hb, w2, Cb);
    rownorm_kernel<<<KCODES / 8, 256>>>();
    colsum_c_kernel<<<KCODES / 64, 256>>>();

    // main fused distance GEMM + argmin
    gemm_nt_kernel<2><<<dim3(KCODES / BN, NROWS / BM), 256>>>(zf, Cb, nullptr);

    gather_kernel<<<NROWS / 8, 256>>>();
    transpose_out_kernel<<<dim3(HW / 32, Dd / 32, Bb * Tt), dim3(32, 8)>>>(out);
    finalize_kernel<<<1, 256>>>(out + (size_t)Bb * Dd * Tt * HW);
}